// round 8
// baseline (speedup 1.0000x reference)
#include <cuda_runtime.h>
#include <math.h>
#include <cstdint>

#define BB 64
#define TT 512
#define HH 1024
#define BT (BB*TT)
#define NF 128
#define N3H (3*HH)
#define GRID 296
#define NTHR 256
#define RPB1 111   // ceil(BT/GRID)

// ---------------- device scratch (no allocations allowed) ----------------
__device__ float g_part_sum[GRID][HH];
__device__ float g_part_sq[GRID][HH];
__device__ float g_a[HH];
__device__ float g_redC[64];      // per-block partial C sums
__device__ float g_redW[64];      // per-block partial sum|Wp|
__device__ unsigned g_pxmax_u;
__device__ float g_pxT[TT][BB];   // px transposed [t][b]
__device__ float g_phi[NF][HH];
__device__ float g_gip[4][NF][N3H];   // K-split GEMM partials
__device__ float g_Ftab[NF];

// ---------------- grid-wide barrier (296 CTAs, 2/SM co-resident) ----------------
__device__ unsigned g_bar_count = 0;
__device__ volatile unsigned g_bar_gen = 0;

__device__ __forceinline__ void grid_sync() {
    __syncthreads();
    if (threadIdx.x == 0) {
        __threadfence();
        unsigned gen = g_bar_gen;
        if (atomicAdd(&g_bar_count, 1u) == GRID - 1) {
            g_bar_count = 0;
            __threadfence();
            g_bar_gen = gen + 1;
        } else {
            while (g_bar_gen == gen) { }
        }
        __threadfence();
    }
    __syncthreads();
}

// fixed-order 64-way sum, L1-bypassing (lines are multi-writer)
__device__ __forceinline__ float sum64_cg(const float* p) {
    float s = 0.f;
#pragma unroll
    for (int i = 0; i < 64; i++) s += __ldcg(p + i);
    return s;
}
// R computed bit-identically wherever needed
__device__ __forceinline__ float load_R(float bp0) {
    float wl = sum64_cg(g_redW) + fabsf(bp0);
    float pxmax = __uint_as_float(__ldcg((const unsigned*)&g_pxmax_u));
    return 0.5f * (pxmax + wl) * 1.02f + 0.25f;
}

__global__ void __launch_bounds__(NTHR, 2) k_fused(
    const float* __restrict__ x,
    const float* __restrict__ gamma, const float* __restrict__ beta,
    const float* __restrict__ W0, const float* __restrict__ bih0,
    const float* __restrict__ bhh0,
    const float* __restrict__ W1, const float* __restrict__ bih1,
    const float* __restrict__ bhh1,
    const float* __restrict__ Wp, const float* __restrict__ bp,
    float* __restrict__ out)
{
    __shared__ __align__(16) float s_buf[2176];  // union: gemm tiles / reductions / scan table
    int b = blockIdx.x, tid = threadIdx.x;

    // ======== phase 1: BN partial sums (all 296 blocks, ~111 rows each) ========
    {
        int r0 = b * RPB1, r1 = r0 + RPB1; if (r1 > BT) r1 = BT;
        float s0=0.f,s1=0.f,s2=0.f,s3=0.f,q0=0.f,q1=0.f,q2=0.f,q3=0.f;
        const float* p = x + (size_t)r0 * HH + tid;
#pragma unroll 4
        for (int r = r0; r < r1; r++, p += HH) {
            float v0 = p[0], v1 = p[256], v2 = p[512], v3 = p[768];
            s0 += v0; q0 += v0*v0; s1 += v1; q1 += v1*v1;
            s2 += v2; q2 += v2*v2; s3 += v3; q3 += v3*v3;
        }
        g_part_sum[b][tid]     = s0; g_part_sq[b][tid]     = q0;
        g_part_sum[b][tid+256] = s1; g_part_sq[b][tid+256] = q1;
        g_part_sum[b][tid+512] = s2; g_part_sq[b][tid+512] = q2;
        g_part_sum[b][tid+768] = s3; g_part_sq[b][tid+768] = q3;
        if (b == 0 && tid == 0) g_pxmax_u = 0u;   // per-replay reset
    }
    grid_sync();

    // ======== phase 2: finalize -> a[], partial C / |Wp| sums (blocks 0..63) ========
    if (b < 64) {
        int ch_l = tid >> 4;          // 16 channels per block
        int part = tid & 15;          // 16 partial-summers per channel
        int j = b * 16 + ch_l;
        float s = 0.f, q = 0.f;
        for (int c = part; c < GRID; c += 16) {
            s += __ldcg(&g_part_sum[c][j]);
            q += __ldcg(&g_part_sq[c][j]);
        }
#pragma unroll
        for (int off = 8; off; off >>= 1) {
            s += __shfl_down_sync(0xFFFFFFFFu, s, off, 16);
            q += __shfl_down_sync(0xFFFFFFFFu, q, off, 16);
        }
        if (part == 0) {
            float mean = s * (1.0f / BT);
            float var  = q * (1.0f / BT) - mean * mean;
            float rstd = rsqrtf(var + 1e-5f);
            float gj = gamma[j], wj = Wp[j];
            g_a[j] = gj * rstd * wj;
            s_buf[ch_l]      = (beta[j] - mean * rstd * gj) * wj;   // cj
            s_buf[16 + ch_l] = fabsf(wj);
        }
        __syncthreads();
        if (tid == 0) {
            float sc = 0.f, sw = 0.f;
#pragma unroll
            for (int i = 0; i < 16; i++) { sc += s_buf[i]; sw += s_buf[16 + i]; }
            g_redC[b] = sc; g_redW[b] = sw;
        }
    }
    grid_sync();

    // ======== phase 3: px (descending rows for L2 reuse of phase-1 tail) ========
    {
        float C = sum64_cg(g_redC) + bp[0];
        int w = tid >> 5, lane = tid & 31;
        int r0 = b * RPB1, r1 = r0 + RPB1; if (r1 > BT) r1 = BT;
        float4 areg[8];
#pragma unroll
        for (int i = 0; i < 8; i++) areg[i] = __ldcg((const float4*)g_a + lane + i * 32);
        float mymax = 0.f;
        for (int r = r1 - 1 - w; r >= r0; r -= 8) {
            const float4* xr = (const float4*)(x + (size_t)r * HH);
            float acc = 0.f;
#pragma unroll
            for (int i = 0; i < 8; i++) {
                float4 xv = xr[lane + i * 32];
                acc += xv.x*areg[i].x + xv.y*areg[i].y + xv.z*areg[i].z + xv.w*areg[i].w;
            }
#pragma unroll
            for (int o = 16; o; o >>= 1) acc += __shfl_down_sync(0xFFFFFFFFu, acc, o);
            if (lane == 0) {
                float v = acc + C;
                g_pxT[r & (TT - 1)][r >> 9] = v;
                mymax = fmaxf(mymax, fabsf(v));
            }
        }
        __syncthreads();
        if (lane == 0) s_buf[w] = mymax;
        __syncthreads();
        if (tid == 0) {
            float m = fmaxf(fmaxf(fmaxf(s_buf[0], s_buf[1]), fmaxf(s_buf[2], s_buf[3])),
                            fmaxf(fmaxf(s_buf[4], s_buf[5]), fmaxf(s_buf[6], s_buf[7])));
            atomicMax(&g_pxmax_u, __float_as_uint(m));   // m>=0: uint order == float order
        }
    }
    grid_sync();

    // ======== phase 4: phi table (layer-0 GRU cell, h=0) ========
    {
        float R = load_R(bp[0]);
        float s0v = -R, delta = 2.f * R / (float)(NF - 1);
        for (int idx = b * NTHR + tid; idx < NF * HH; idx += GRID * NTHR) {
            int i = idx >> 10, j = idx & (HH - 1);
            float s = s0v + (float)i * delta;
            float ar = fmaf(s, W0[j],          bih0[j]        + bhh0[j]);
            float az = fmaf(s, W0[HH + j],     bih0[HH + j]   + bhh0[HH + j]);
            float r = 1.f / (1.f + expf(-ar));
            float z = 1.f / (1.f + expf(-az));
            float an = fmaf(s, W0[2*HH + j], fmaf(r, bhh0[2*HH + j], bih0[2*HH + j]));
            g_phi[i][j] = (1.f - z) * tanhf(an);
        }
    }
    grid_sync();

    // ======== phase 5: FFMA GEMM, K-split 4 -> 384 jobs of 64x64xK256 ========
    {
        float (*As)[68] = (float (*)[68])s_buf;
        float (*Bs)[68] = (float (*)[68])(s_buf + 1088);
        int lrow = tid >> 2, lk4 = (tid & 3) * 4;
        int mt = (tid >> 4) * 4, nt = (tid & 15) * 4;
        int njobs = (b < 384 - GRID) ? 2 : 1;
        for (int jj = 0; jj < njobs; jj++) {
            int job = b + jj * GRID;                    // 0..383
            int kseg = job / 96, rem = job % 96;
            int m0 = (rem & 1) * 64, n0 = (rem >> 1) * 64;
            float acc[4][4] = {};
            for (int k0 = kseg * 256; k0 < kseg * 256 + 256; k0 += 16) {
                float4 av = *(const float4*)&g_phi[m0 + lrow][k0 + lk4];
                float4 bv = *(const float4*)&W1[(size_t)(n0 + lrow) * HH + k0 + lk4];
                As[lk4 + 0][lrow] = av.x; As[lk4 + 1][lrow] = av.y;
                As[lk4 + 2][lrow] = av.z; As[lk4 + 3][lrow] = av.w;
                Bs[lk4 + 0][lrow] = bv.x; Bs[lk4 + 1][lrow] = bv.y;
                Bs[lk4 + 2][lrow] = bv.z; Bs[lk4 + 3][lrow] = bv.w;
                __syncthreads();
#pragma unroll
                for (int kk = 0; kk < 16; kk++) {
                    float4 a4v = *(const float4*)&As[kk][mt];
                    float4 b4v = *(const float4*)&Bs[kk][nt];
                    float a_[4] = {a4v.x, a4v.y, a4v.z, a4v.w};
                    float b_[4] = {b4v.x, b4v.y, b4v.z, b4v.w};
#pragma unroll
                    for (int r = 0; r < 4; r++)
#pragma unroll
                        for (int c = 0; c < 4; c++)
                            acc[r][c] = fmaf(a_[r], b_[c], acc[r][c]);
                }
                __syncthreads();
            }
#pragma unroll
            for (int r = 0; r < 4; r++) {
                float4 o = make_float4(acc[r][0], acc[r][1], acc[r][2], acc[r][3]);
                *(float4*)&g_gip[kseg][m0 + mt + r][n0 + nt] = o;
            }
        }
    }
    grid_sync();

    // ======== phase 6: sum K-partials + layer-1 nonlin + projection (blocks 0..127) ========
    if (b < NF) {
        float acc = 0.f;
        for (int ch = tid; ch < HH; ch += NTHR) {
            float gr = ((__ldcg(&g_gip[0][b][ch])        + __ldcg(&g_gip[1][b][ch])) +
                        (__ldcg(&g_gip[2][b][ch])        + __ldcg(&g_gip[3][b][ch]))) + bih1[ch];
            float gz = ((__ldcg(&g_gip[0][b][HH + ch])   + __ldcg(&g_gip[1][b][HH + ch])) +
                        (__ldcg(&g_gip[2][b][HH + ch])   + __ldcg(&g_gip[3][b][HH + ch]))) + bih1[HH + ch];
            float gn = ((__ldcg(&g_gip[0][b][2*HH + ch]) + __ldcg(&g_gip[1][b][2*HH + ch])) +
                        (__ldcg(&g_gip[2][b][2*HH + ch]) + __ldcg(&g_gip[3][b][2*HH + ch]))) + bih1[2*HH + ch];
            float r = 1.f / (1.f + expf(-(gr + bhh1[ch])));
            float z = 1.f / (1.f + expf(-(gz + bhh1[HH + ch])));
            float n = tanhf(gn + r * bhh1[2*HH + ch]);
            acc += Wp[ch] * (1.f - z) * n;
        }
        s_buf[tid] = acc;
        __syncthreads();
        for (int st = 128; st > 0; st >>= 1) {
            if (tid < st) s_buf[tid] += s_buf[tid + st];
            __syncthreads();
        }
        if (tid == 0) g_Ftab[b] = s_buf[0] + bp[0];
    }
    grid_sync();

    // ======== phase 7: sequential scan, 64 scalar recurrences (block 0) ========
    if (b == 0) {
        float4* tab4 = (float4*)s_buf;
        for (int i = tid; i < NF; i += NTHR) {
            float p0 = __ldcg(&g_Ftab[i > 0 ? i - 1 : 0]);
            float p1 = __ldcg(&g_Ftab[i]);
            float p2 = __ldcg(&g_Ftab[i < NF - 1 ? i + 1 : NF - 1]);
            float p3 = __ldcg(&g_Ftab[i < NF - 2 ? i + 2 : NF - 1]);
            tab4[i] = make_float4(p0, p1, p2, p3);
        }
        __syncthreads();
        if (tid < BB) {
            float R = load_R(bp[0]);
            float invd = (float)(NF - 1) / (2.f * R);
            float k1 = 0.5f * invd;
            float base = R * invd - 0.5f;        // -0.5: round(u') == floor(true_u)
            const float MAGIC = 12582912.0f;     // 2^23 + 2^22
            float* o = out + tid * TT;
            float f = 0.f;
            float buf[8];
#pragma unroll
            for (int i = 0; i < 8; i++) buf[i] = __ldcg(&g_pxT[i][tid]);
            for (int t0 = 0; t0 < TT; t0 += 8) {
#pragma unroll
                for (int i = 0; i < 8; i++) {
                    float pxv = buf[i];
                    int tn = t0 + 8 + i;
                    if (tn < TT) buf[i] = __ldcg(&g_pxT[tn][tid]);  // off the f-chain
                    float pb = fmaf(pxv, k1, base);                 // independent of f
                    float u = fmaf(f, k1, pb);                      // = true_u - 0.5
                    float fm = u + MAGIC;
                    int idx = __float_as_int(fm) & 0x7F;            // floor(true_u) in [1,126]
                    float idxf = fm - MAGIC;
                    float y = u - idxf;                             // in [-0.5, 0.5)
                    float4 P = tab4[idx];
                    float xx  = y + 0.5f;
                    float xm1 = y - 0.5f;
                    float xm2 = y - 1.5f;
                    float xp1 = y + 1.5f;
                    float w0 = -xx  * xm1 * xm2 * (1.f / 6.f);
                    float w1 =  xp1 * xm1 * xm2 * 0.5f;
                    float w2 = -xp1 * xx  * xm2 * 0.5f;
                    float w3 =  xp1 * xx  * xm1 * (1.f / 6.f);
                    float a0 = w0 * P.x, a1 = w1 * P.y, a2 = w2 * P.z, a3 = w3 * P.w;
                    f = (a0 + a1) + (a2 + a3);
                    o[t0 + i] = f;
                }
            }
        }
    }
}

extern "C" void kernel_launch(void* const* d_in, const int* in_sizes, int n_in,
                              void* d_out, int out_size) {
    const float* x     = (const float*)d_in[0];
    // d_in[1] timestamp: unused
    const float* gamma = (const float*)d_in[2];
    const float* beta  = (const float*)d_in[3];
    const float* Wih0  = (const float*)d_in[4];
    const float* bih0  = (const float*)d_in[5];
    // d_in[6] W_hh0 unused (h_prev = 0)
    const float* bhh0  = (const float*)d_in[7];
    const float* Wih1  = (const float*)d_in[8];
    const float* bih1  = (const float*)d_in[9];
    // d_in[10] W_hh1 unused
    const float* bhh1  = (const float*)d_in[11];
    const float* Wp    = (const float*)d_in[12];
    const float* bp    = (const float*)d_in[13];
    float* out = (float*)d_out;

    k_fused<<<GRID, NTHR>>>(x, gamma, beta, Wih0, bih0, bhh0,
                            Wih1, bih1, bhh1, Wp, bp, out);
}

// round 9
// speedup vs baseline: 1.1242x; 1.1242x over previous
#include <cuda_runtime.h>
#include <cuda_fp16.h>
#include <mma.h>
#include <math.h>
#include <cstdint>

using namespace nvcuda;

#define BB 64
#define TT 512
#define HH 1024
#define BT (BB*TT)
#define NF 128
#define N3H (3*HH)
#define GRID 148
#define NTHR 512
#define RPB 222    // ceil(BT/GRID)

// ---------------- device scratch (no allocations allowed) ----------------
__device__ float g_part_sum[GRID][HH];
__device__ float g_part_sq[GRID][HH];
__device__ float g_a[HH];
__device__ float g_redC[64];
__device__ float g_redW[64];
__device__ unsigned g_pxmax_u;
__device__ float g_pxT[TT][BB];     // px transposed [t][b]
__device__ float g_phi[NF][HH];
__device__ float g_gip[2][NF][N3H]; // 2-way K-split GEMM partials
__device__ float g_Ftab[NF];

// ---------------- grid-wide barrier (148 CTAs, 1/SM) ----------------
__device__ unsigned g_bar_count = 0;
__device__ volatile unsigned g_bar_gen = 0;

__device__ __forceinline__ void grid_sync() {
    __syncthreads();
    if (threadIdx.x == 0) {
        __threadfence();
        unsigned gen = g_bar_gen;
        if (atomicAdd(&g_bar_count, 1u) == GRID - 1) {
            g_bar_count = 0;
            __threadfence();
            g_bar_gen = gen + 1;
        } else {
            while (g_bar_gen == gen) { }
        }
        __threadfence();
    }
    __syncthreads();
}

// half-block barrier (256 threads), id 1 or 2
__device__ __forceinline__ void half_bar(int id) {
    asm volatile("bar.sync %0, 256;" :: "r"(id) : "memory");
}

__device__ __forceinline__ float sum64_cg(const float* p) {
    float s = 0.f;
#pragma unroll
    for (int i = 0; i < 64; i++) s += __ldcg(p + i);
    return s;
}
__device__ __forceinline__ float load_R(float bp0) {
    float wl = sum64_cg(g_redW) + fabsf(bp0);
    float pxmax = __uint_as_float(__ldcg((const unsigned*)&g_pxmax_u));
    return 0.5f * (pxmax + wl) * 1.02f + 0.25f;
}

#define LDMH 72    // fp16 smem row stride (144B, 16B-multiple)

__global__ void __launch_bounds__(NTHR, 1) k_fused(
    const float* __restrict__ x,
    const float* __restrict__ gamma, const float* __restrict__ beta,
    const float* __restrict__ W0, const float* __restrict__ bih0,
    const float* __restrict__ bhh0,
    const float* __restrict__ W1, const float* __restrict__ bih1,
    const float* __restrict__ bhh1,
    const float* __restrict__ Wp, const float* __restrict__ bp,
    float* __restrict__ out)
{
    __shared__ __align__(16) char s_mem[36992];   // union: gemm fp16 tiles / reductions / scan table
    float* s_buf = (float*)s_mem;
    int b = blockIdx.x, tid = threadIdx.x;

    // ======== phase 1: BN partial sums (148 blocks x 222 rows, 512 thr: 2 ch each) ========
    {
        int r0 = b * RPB, r1 = r0 + RPB; if (r1 > BT) r1 = BT;
        float s0 = 0.f, q0 = 0.f, s1 = 0.f, q1 = 0.f;
        const float* p = x + (size_t)r0 * HH + tid;
#pragma unroll 8
        for (int r = r0; r < r1; r++, p += HH) {
            float v0 = p[0], v1 = p[512];
            s0 += v0; q0 += v0 * v0;
            s1 += v1; q1 += v1 * v1;
        }
        g_part_sum[b][tid]       = s0; g_part_sq[b][tid]       = q0;
        g_part_sum[b][tid + 512] = s1; g_part_sq[b][tid + 512] = q1;
        if (b == 0 && tid == 0) g_pxmax_u = 0u;   // per-replay reset
    }
    grid_sync();

    // ======== phase 2: finalize -> a[], partial C / |Wp| (blocks 0..63) ========
    if (b < 64) {
        int ch_l = tid >> 5;          // 16 channels per block
        int part = tid & 31;          // 32 partial-summers per channel
        int j = b * 16 + ch_l;
        float s = 0.f, q = 0.f;
        for (int c = part; c < GRID; c += 32) {
            s += __ldcg(&g_part_sum[c][j]);
            q += __ldcg(&g_part_sq[c][j]);
        }
#pragma unroll
        for (int off = 16; off; off >>= 1) {
            s += __shfl_down_sync(0xFFFFFFFFu, s, off);
            q += __shfl_down_sync(0xFFFFFFFFu, q, off);
        }
        if (part == 0) {
            float mean = s * (1.0f / BT);
            float var  = q * (1.0f / BT) - mean * mean;
            float rstd = rsqrtf(var + 1e-5f);
            float gj = gamma[j], wj = Wp[j];
            g_a[j] = gj * rstd * wj;
            s_buf[ch_l]      = (beta[j] - mean * rstd * gj) * wj;
            s_buf[16 + ch_l] = fabsf(wj);
        }
        __syncthreads();
        if (tid == 0) {
            float sc = 0.f, sw = 0.f;
#pragma unroll
            for (int i = 0; i < 16; i++) { sc += s_buf[i]; sw += s_buf[16 + i]; }
            g_redC[b] = sc; g_redW[b] = sw;
        }
    }
    grid_sync();

    // ======== phase 3: px (ascending, 16 warps/CTA) ========
    {
        float C = sum64_cg(g_redC) + bp[0];
        int w = tid >> 5, lane = tid & 31;
        int r0 = b * RPB, r1 = r0 + RPB; if (r1 > BT) r1 = BT;
        float4 areg[8];
#pragma unroll
        for (int i = 0; i < 8; i++) areg[i] = __ldcg((const float4*)g_a + lane + i * 32);
        float mymax = 0.f;
        for (int r = r0 + w; r < r1; r += 16) {
            const float4* xr = (const float4*)(x + (size_t)r * HH);
            float acc = 0.f;
#pragma unroll
            for (int i = 0; i < 8; i++) {
                float4 xv = xr[lane + i * 32];
                acc += xv.x*areg[i].x + xv.y*areg[i].y + xv.z*areg[i].z + xv.w*areg[i].w;
            }
#pragma unroll
            for (int o = 16; o; o >>= 1) acc += __shfl_down_sync(0xFFFFFFFFu, acc, o);
            if (lane == 0) {
                float v = acc + C;
                g_pxT[r & (TT - 1)][r >> 9] = v;
                mymax = fmaxf(mymax, fabsf(v));
            }
        }
        __syncthreads();
        if (lane == 0) s_buf[w] = mymax;
        __syncthreads();
        if (tid == 0) {
            float m = s_buf[0];
#pragma unroll
            for (int i = 1; i < 16; i++) m = fmaxf(m, s_buf[i]);
            atomicMax(&g_pxmax_u, __float_as_uint(m));   // m>=0: uint order == float order
        }
    }
    grid_sync();

    // ======== phase 4: phi table (layer-0 GRU cell, h=0) ========
    {
        float R = load_R(bp[0]);
        float s0v = -R, delta = 2.f * R / (float)(NF - 1);
        for (int idx = b * NTHR + tid; idx < NF * HH; idx += GRID * NTHR) {
            int i = idx >> 10, j = idx & (HH - 1);
            float s = s0v + (float)i * delta;
            float ar = fmaf(s, W0[j],          bih0[j]        + bhh0[j]);
            float az = fmaf(s, W0[HH + j],     bih0[HH + j]   + bhh0[HH + j]);
            float r = 1.f / (1.f + expf(-ar));
            float z = 1.f / (1.f + expf(-az));
            float an = fmaf(s, W0[2*HH + j], fmaf(r, bhh0[2*HH + j], bih0[2*HH + j]));
            g_phi[i][j] = (1.f - z) * tanhf(an);
        }
    }
    grid_sync();

    // ======== phase 5: fp16 WMMA GEMM, 192 jobs 64x64xK512, 2 jobs/block in halves ========
    {
        int half = tid >> 8;          // 0 / 1
        int ltid = tid & 255;
        int job = b + half * GRID;    // 0..295
        if (job < 192) {
            __half (*As)[LDMH] = (__half(*)[LDMH])(s_mem + half * 18496);
            __half (*Bs)[LDMH] = (__half(*)[LDMH])(s_mem + half * 18496 + 9248);
            int kseg = job / 96, rem = job % 96;
            int m0 = (rem & 1) * 64, n0 = (rem >> 1) * 64;
            int w = ltid >> 5;              // 0..7
            int wm = w >> 1, wn = w & 1;    // 4 x 2 warp grid, warp tile 16x32
            int sr = ltid >> 2;             // staging row 0..63
            int sc = (ltid & 3) * 16;       // staging col base

            wmma::fragment<wmma::accumulator, 16, 16, 16, float> acc[2];
            wmma::fill_fragment(acc[0], 0.0f);
            wmma::fill_fragment(acc[1], 0.0f);

            for (int kc = 0; kc < 8; kc++) {
                int k0 = kseg * 512 + kc * 64;
                half_bar(half + 1);          // prior chunk reads done
                const float4* pa = (const float4*)&g_phi[m0 + sr][k0] + (sc >> 2);
                const float4* pb = (const float4*)&W1[(size_t)(n0 + sr) * HH + k0] + (sc >> 2);
#pragma unroll
                for (int j = 0; j < 4; j++) {
                    float4 va = pa[j];
                    union { __half2 h[2]; uint2 u; } ta;
                    ta.h[0] = __floats2half2_rn(va.x, va.y);
                    ta.h[1] = __floats2half2_rn(va.z, va.w);
                    *(uint2*)&As[sr][sc + j * 4] = ta.u;
                    float4 vb = pb[j];
                    union { __half2 h[2]; uint2 u; } tb;
                    tb.h[0] = __floats2half2_rn(vb.x, vb.y);
                    tb.h[1] = __floats2half2_rn(vb.z, vb.w);
                    *(uint2*)&Bs[sr][sc + j * 4] = tb.u;
                }
                half_bar(half + 1);          // tiles staged
#pragma unroll
                for (int ks = 0; ks < 4; ks++) {
                    int kk = ks * 16;
                    wmma::fragment<wmma::matrix_a, 16, 16, 16, __half, wmma::row_major> fa;
                    wmma::fragment<wmma::matrix_b, 16, 16, 16, __half, wmma::col_major> fb0, fb1;
                    wmma::load_matrix_sync(fa,  &As[wm * 16][kk], LDMH);
                    wmma::load_matrix_sync(fb0, &Bs[wn * 32][kk], LDMH);
                    wmma::load_matrix_sync(fb1, &Bs[wn * 32 + 16][kk], LDMH);
                    wmma::mma_sync(acc[0], fa, fb0, acc[0]);
                    wmma::mma_sync(acc[1], fa, fb1, acc[1]);
                }
            }
            wmma::store_matrix_sync(&g_gip[kseg][m0 + wm * 16][n0 + wn * 32],
                                    acc[0], N3H, wmma::mem_row_major);
            wmma::store_matrix_sync(&g_gip[kseg][m0 + wm * 16][n0 + wn * 32 + 16],
                                    acc[1], N3H, wmma::mem_row_major);
        }
    }
    grid_sync();

    // ======== phase 6: sum K-partials + layer-1 nonlin + projection (blocks 0..127) ========
    if (b < NF) {
        float acc = 0.f;
#pragma unroll
        for (int ch = tid; ch < HH; ch += NTHR) {
            float gr = (__ldcg(&g_gip[0][b][ch])        + __ldcg(&g_gip[1][b][ch]))        + bih1[ch];
            float gz = (__ldcg(&g_gip[0][b][HH + ch])   + __ldcg(&g_gip[1][b][HH + ch]))   + bih1[HH + ch];
            float gn = (__ldcg(&g_gip[0][b][2*HH + ch]) + __ldcg(&g_gip[1][b][2*HH + ch])) + bih1[2*HH + ch];
            float r = 1.f / (1.f + expf(-(gr + bhh1[ch])));
            float z = 1.f / (1.f + expf(-(gz + bhh1[HH + ch])));
            float n = tanhf(gn + r * bhh1[2*HH + ch]);
            acc += Wp[ch] * (1.f - z) * n;
        }
        s_buf[tid] = acc;
        __syncthreads();
        for (int st = 256; st > 0; st >>= 1) {
            if (tid < st) s_buf[tid] += s_buf[tid + st];
            __syncthreads();
        }
        if (tid == 0) g_Ftab[b] = s_buf[0] + bp[0];
    }
    grid_sync();

    // ======== phase 7: sequential scan, 64 scalar recurrences (block 0) ========
    if (b == 0) {
        float4* tab4 = (float4*)s_buf;
        for (int i = tid; i < NF; i += NTHR) {
            float p0 = __ldcg(&g_Ftab[i > 0 ? i - 1 : 0]);
            float p1 = __ldcg(&g_Ftab[i]);
            float p2 = __ldcg(&g_Ftab[i < NF - 1 ? i + 1 : NF - 1]);
            float p3 = __ldcg(&g_Ftab[i < NF - 2 ? i + 2 : NF - 1]);
            tab4[i] = make_float4(p0, p1, p2, p3);
        }
        __syncthreads();
        if (tid < BB) {
            float R = load_R(bp[0]);
            float invd = (float)(NF - 1) / (2.f * R);
            float k1 = 0.5f * invd;
            float base = R * invd - 0.5f;        // -0.5: round(u') == floor(true_u)
            const float MAGIC = 12582912.0f;     // 2^23 + 2^22
            float* o = out + tid * TT;
            float f = 0.f;
            float buf[8];
#pragma unroll
            for (int i = 0; i < 8; i++) buf[i] = __ldcg(&g_pxT[i][tid]);
            for (int t0 = 0; t0 < TT; t0 += 8) {
#pragma unroll
                for (int i = 0; i < 8; i++) {
                    float pxv = buf[i];
                    int tn = t0 + 8 + i;
                    if (tn < TT) buf[i] = __ldcg(&g_pxT[tn][tid]);  // off the f-chain
                    float pb = fmaf(pxv, k1, base);                 // independent of f
                    float u = fmaf(f, k1, pb);                      // = true_u - 0.5
                    float fm = u + MAGIC;
                    int idx = __float_as_int(fm) & 0x7F;            // floor(true_u) in [1,126]
                    float idxf = fm - MAGIC;
                    float y = u - idxf;                             // in [-0.5, 0.5)
                    float4 P = tab4[idx];
                    float xx  = y + 0.5f;
                    float xm1 = y - 0.5f;
                    float xm2 = y - 1.5f;
                    float xp1 = y + 1.5f;
                    float w0 = -xx  * xm1 * xm2 * (1.f / 6.f);
                    float w1 =  xp1 * xm1 * xm2 * 0.5f;
                    float w2 = -xp1 * xx  * xm2 * 0.5f;
                    float w3 =  xp1 * xx  * xm1 * (1.f / 6.f);
                    float a0 = w0 * P.x, a1 = w1 * P.y, a2 = w2 * P.z, a3 = w3 * P.w;
                    f = (a0 + a1) + (a2 + a3);
                    o[t0 + i] = f;
                }
            }
        }
    }
}

extern "C" void kernel_launch(void* const* d_in, const int* in_sizes, int n_in,
                              void* d_out, int out_size) {
    const float* x     = (const float*)d_in[0];
    // d_in[1] timestamp: unused
    const float* gamma = (const float*)d_in[2];
    const float* beta  = (const float*)d_in[3];
    const float* Wih0  = (const float*)d_in[4];
    const float* bih0  = (const float*)d_in[5];
    // d_in[6] W_hh0 unused (h_prev = 0)
    const float* bhh0  = (const float*)d_in[7];
    const float* Wih1  = (const float*)d_in[8];
    const float* bih1  = (const float*)d_in[9];
    // d_in[10] W_hh1 unused
    const float* bhh1  = (const float*)d_in[11];
    const float* Wp    = (const float*)d_in[12];
    const float* bp    = (const float*)d_in[13];
    float* out = (float*)d_out;

    k_fused<<<GRID, NTHR>>>(x, gamma, beta, Wih0, bih0, bhh0,
                            Wih1, bih1, bhh1, Wp, bp, out);
}

// round 10
// speedup vs baseline: 1.6931x; 1.5060x over previous
#include <cuda_runtime.h>
#include <cuda_fp16.h>
#include <mma.h>
#include <math.h>
#include <cstdint>

using namespace nvcuda;

#define BB 64
#define TT 512
#define HH 1024
#define BT (BB*TT)
#define NF 128
#define N3H (3*HH)
#define NCHUNK 64
#define ROWS_PER_CHUNK (BT/NCHUNK)  // 512
#define GRID 148
#define NTHR 512

// ---------------- device scratch (no allocations allowed) ----------------
__device__ float g_part_sum[NCHUNK][HH];
__device__ float g_part_sq[NCHUNK][HH];
__device__ float g_a[HH];
__device__ float g_C;
__device__ float g_WpL1;            // sum|Wp| + |bp|
__device__ unsigned g_pxmax_u;
__device__ float g_pxT[TT][BB];     // px transposed [t][b]
__device__ float g_phi[NF][HH];
__device__ float g_gip[2][NF][N3H]; // 2-way K-split GEMM partials
__device__ float g_Ftab[NF];

// ---------------- grid-wide barrier for the fused tail (148 CTAs, 1/SM) ----------------
__device__ unsigned g_bar_count = 0;
__device__ volatile unsigned g_bar_gen = 0;

__device__ __forceinline__ void grid_sync() {
    __syncthreads();
    if (threadIdx.x == 0) {
        __threadfence();
        unsigned gen = g_bar_gen;
        if (atomicAdd(&g_bar_count, 1u) == GRID - 1) {
            g_bar_count = 0;
            __threadfence();
            g_bar_gen = gen + 1;
        } else {
            while (g_bar_gen == gen) { }
        }
        __threadfence();
    }
    __syncthreads();
}

__device__ __forceinline__ void half_bar(int id) {
    asm volatile("bar.sync %0, 256;" :: "r"(id) : "memory");
}

__device__ __forceinline__ float load_R() {
    float wl = __ldcg(&g_WpL1);
    float pxmax = __uint_as_float(__ldcg((const unsigned*)&g_pxmax_u));
    return 0.5f * (pxmax + wl) * 1.02f + 0.25f;
}

// ================= pass 1: BN partial sums (R2-proven wide grid) =================
__global__ void k_stats(const float* __restrict__ x) {
    int ch = blockIdx.x * 256 + threadIdx.x;
    int r0 = blockIdx.y * ROWS_PER_CHUNK;
    const float* p = x + (size_t)r0 * HH + ch;
    float s = 0.f, q = 0.f;
#pragma unroll 16
    for (int r = 0; r < ROWS_PER_CHUNK; r++) {
        float v = p[(size_t)r * HH];
        s += v; q += v * v;
    }
    g_part_sum[blockIdx.y][ch] = s;
    g_part_sq[blockIdx.y][ch]  = q;
}

// ================= finalize -> a[], C, WpL1; reset pxmax =================
__global__ void k_finalize(const float* __restrict__ gamma, const float* __restrict__ beta,
                           const float* __restrict__ Wp, const float* __restrict__ bp) {
    int j = threadIdx.x;  // 1024
    float s = 0.f, q = 0.f;
#pragma unroll 8
    for (int c = 0; c < NCHUNK; c++) { s += g_part_sum[c][j]; q += g_part_sq[c][j]; }
    float mean = s * (1.0f / BT);
    float var  = q * (1.0f / BT) - mean * mean;
    float rstd = rsqrtf(var + 1e-5f);
    float gj = gamma[j], wj = Wp[j];
    g_a[j] = gj * rstd * wj;
    float cj = (beta[j] - mean * rstd * gj) * wj;
    float aw = fabsf(wj);
    __shared__ float sc[1024], sa[1024];
    sc[j] = cj; sa[j] = aw;
    __syncthreads();
    for (int st = 512; st > 0; st >>= 1) {
        if (j < st) { sc[j] += sc[j + st]; sa[j] += sa[j + st]; }
        __syncthreads();
    }
    if (j == 0) {
        g_C = sc[0] + bp[0];
        g_WpL1 = sa[0] + fabsf(bp[0]);
        g_pxmax_u = 0u;   // per-replay reset
    }
}

// ================= pass 2: px -> transposed store + global max (R2-proven) =================
__global__ void k_px(const float* __restrict__ x) {
    int w = threadIdx.x >> 5, lane = threadIdx.x & 31;
    int r = blockIdx.x * 8 + w;
    const float4* xr = (const float4*)(x + (size_t)r * HH);
    const float4* a4 = (const float4*)g_a;
    float acc = 0.f;
#pragma unroll
    for (int i = 0; i < 8; i++) {
        float4 xv = xr[lane + i * 32];
        float4 av = __ldg(&a4[lane + i * 32]);
        acc += xv.x * av.x + xv.y * av.y + xv.z * av.z + xv.w * av.w;
    }
#pragma unroll
    for (int off = 16; off; off >>= 1) acc += __shfl_down_sync(0xFFFFFFFFu, acc, off);
    __shared__ float wm[8];
    if (lane == 0) {
        float v = acc + g_C;
        g_pxT[r & (TT - 1)][r >> 9] = v;
        wm[w] = fabsf(v);
    }
    __syncthreads();
    if (threadIdx.x == 0) {
        float m = wm[0];
#pragma unroll
        for (int i = 1; i < 8; i++) m = fmaxf(m, wm[i]);
        atomicMax(&g_pxmax_u, __float_as_uint(m));   // m>=0: uint order == float order
    }
}

// ================= fused tail: phi -> fp16 WMMA GEMM -> tail -> scan =================
#define LDMH 72    // fp16 smem row stride (144B)

__global__ void __launch_bounds__(NTHR, 1) k_tabscan(
    const float* __restrict__ W0, const float* __restrict__ bih0,
    const float* __restrict__ bhh0,
    const float* __restrict__ W1, const float* __restrict__ bih1,
    const float* __restrict__ bhh1,
    const float* __restrict__ Wp, const float* __restrict__ bp,
    float* __restrict__ out)
{
    __shared__ __align__(16) char s_mem[36992];
    float* s_buf = (float*)s_mem;
    int b = blockIdx.x, tid = threadIdx.x;

    // ---- phase A: phi table (layer-0 GRU cell, h=0) ----
    {
        float R = load_R();
        float s0v = -R, delta = 2.f * R / (float)(NF - 1);
        for (int idx = b * NTHR + tid; idx < NF * HH; idx += GRID * NTHR) {
            int i = idx >> 10, j = idx & (HH - 1);
            float s = s0v + (float)i * delta;
            float ar = fmaf(s, W0[j],          bih0[j]        + bhh0[j]);
            float az = fmaf(s, W0[HH + j],     bih0[HH + j]   + bhh0[HH + j]);
            float r = 1.f / (1.f + expf(-ar));
            float z = 1.f / (1.f + expf(-az));
            float an = fmaf(s, W0[2*HH + j], fmaf(r, bhh0[2*HH + j], bih0[2*HH + j]));
            g_phi[i][j] = (1.f - z) * tanhf(an);
        }
    }
    grid_sync();

    // ---- phase B: fp16 WMMA GEMM, 192 jobs 64x64xK512, 2 jobs/block in halves ----
    {
        int half = tid >> 8;          // 0 / 1
        int ltid = tid & 255;
        int job = b + half * GRID;    // 0..295
        if (job < 192) {
            __half (*As)[LDMH] = (__half(*)[LDMH])(s_mem + half * 18496);
            __half (*Bs)[LDMH] = (__half(*)[LDMH])(s_mem + half * 18496 + 9248);
            int kseg = job / 96, rem = job % 96;
            int m0 = (rem & 1) * 64, n0 = (rem >> 1) * 64;
            int w = ltid >> 5;
            int wm = w >> 1, wn = w & 1;    // 4 x 2 warp grid, warp tile 16x32
            int sr = ltid >> 2;
            int sc = (ltid & 3) * 16;

            wmma::fragment<wmma::accumulator, 16, 16, 16, float> acc[2];
            wmma::fill_fragment(acc[0], 0.0f);
            wmma::fill_fragment(acc[1], 0.0f);

            for (int kc = 0; kc < 8; kc++) {
                int k0 = kseg * 512 + kc * 64;
                half_bar(half + 1);
                const float4* pa = (const float4*)&g_phi[m0 + sr][k0] + (sc >> 2);
                const float4* pb = (const float4*)&W1[(size_t)(n0 + sr) * HH + k0] + (sc >> 2);
#pragma unroll
                for (int j = 0; j < 4; j++) {
                    float4 va = pa[j];
                    union { __half2 h[2]; uint2 u; } ta;
                    ta.h[0] = __floats2half2_rn(va.x, va.y);
                    ta.h[1] = __floats2half2_rn(va.z, va.w);
                    *(uint2*)&As[sr][sc + j * 4] = ta.u;
                    float4 vb = pb[j];
                    union { __half2 h[2]; uint2 u; } tb;
                    tb.h[0] = __floats2half2_rn(vb.x, vb.y);
                    tb.h[1] = __floats2half2_rn(vb.z, vb.w);
                    *(uint2*)&Bs[sr][sc + j * 4] = tb.u;
                }
                half_bar(half + 1);
#pragma unroll
                for (int ks = 0; ks < 4; ks++) {
                    int kk = ks * 16;
                    wmma::fragment<wmma::matrix_a, 16, 16, 16, __half, wmma::row_major> fa;
                    wmma::fragment<wmma::matrix_b, 16, 16, 16, __half, wmma::col_major> fb0, fb1;
                    wmma::load_matrix_sync(fa,  &As[wm * 16][kk], LDMH);
                    wmma::load_matrix_sync(fb0, &Bs[wn * 32][kk], LDMH);
                    wmma::load_matrix_sync(fb1, &Bs[wn * 32 + 16][kk], LDMH);
                    wmma::mma_sync(acc[0], fa, fb0, acc[0]);
                    wmma::mma_sync(acc[1], fa, fb1, acc[1]);
                }
            }
            wmma::store_matrix_sync(&g_gip[kseg][m0 + wm * 16][n0 + wn * 32],
                                    acc[0], N3H, wmma::mem_row_major);
            wmma::store_matrix_sync(&g_gip[kseg][m0 + wm * 16][n0 + wn * 32 + 16],
                                    acc[1], N3H, wmma::mem_row_major);
        }
    }
    grid_sync();

    // ---- phase C: sum K-partials + layer-1 nonlin + projection (blocks 0..127) ----
    if (b < NF) {
        float acc = 0.f;
        for (int ch = tid; ch < HH; ch += NTHR) {
            float gr = (__ldcg(&g_gip[0][b][ch])        + __ldcg(&g_gip[1][b][ch]))        + bih1[ch];
            float gz = (__ldcg(&g_gip[0][b][HH + ch])   + __ldcg(&g_gip[1][b][HH + ch]))   + bih1[HH + ch];
            float gn = (__ldcg(&g_gip[0][b][2*HH + ch]) + __ldcg(&g_gip[1][b][2*HH + ch])) + bih1[2*HH + ch];
            float r = 1.f / (1.f + expf(-(gr + bhh1[ch])));
            float z = 1.f / (1.f + expf(-(gz + bhh1[HH + ch])));
            float n = tanhf(gn + r * bhh1[2*HH + ch]);
            acc += Wp[ch] * (1.f - z) * n;
        }
        s_buf[tid] = acc;
        __syncthreads();
        for (int st = 256; st > 0; st >>= 1) {
            if (tid < st) s_buf[tid] += s_buf[tid + st];
            __syncthreads();
        }
        if (tid == 0) g_Ftab[b] = s_buf[0] + bp[0];
    }
    grid_sync();

    // ---- phase D: sequential scan, 64 scalar recurrences (block 0) ----
    if (b == 0) {
        float4* tab4 = (float4*)s_buf;
        for (int i = tid; i < NF; i += NTHR) {
            float p0 = __ldcg(&g_Ftab[i > 0 ? i - 1 : 0]);
            float p1 = __ldcg(&g_Ftab[i]);
            float p2 = __ldcg(&g_Ftab[i < NF - 1 ? i + 1 : NF - 1]);
            float p3 = __ldcg(&g_Ftab[i < NF - 2 ? i + 2 : NF - 1]);
            tab4[i] = make_float4(p0, p1, p2, p3);
        }
        __syncthreads();
        if (tid < BB) {
            float R = load_R();
            float invd = (float)(NF - 1) / (2.f * R);
            float k1 = 0.5f * invd;
            float base = R * invd - 0.5f;        // -0.5: round(u') == floor(true_u)
            const float MAGIC = 12582912.0f;     // 2^23 + 2^22
            float* o = out + tid * TT;
            float f = 0.f;
            float buf[8];
#pragma unroll
            for (int i = 0; i < 8; i++) buf[i] = __ldcg(&g_pxT[i][tid]);
            for (int t0 = 0; t0 < TT; t0 += 8) {
#pragma unroll
                for (int i = 0; i < 8; i++) {
                    float pxv = buf[i];
                    int tn = t0 + 8 + i;
                    if (tn < TT) buf[i] = __ldcg(&g_pxT[tn][tid]);  // off the f-chain
                    float pb = fmaf(pxv, k1, base);                 // independent of f
                    float u = fmaf(f, k1, pb);                      // = true_u - 0.5
                    float fm = u + MAGIC;
                    int idx = __float_as_int(fm) & 0x7F;            // floor(true_u) in [1,126]
                    float idxf = fm - MAGIC;
                    float y = u - idxf;                             // in [-0.5, 0.5)
                    float4 P = tab4[idx];
                    float xx  = y + 0.5f;
                    float xm1 = y - 0.5f;
                    float xm2 = y - 1.5f;
                    float xp1 = y + 1.5f;
                    float w0 = -xx  * xm1 * xm2 * (1.f / 6.f);
                    float w1 =  xp1 * xm1 * xm2 * 0.5f;
                    float w2 = -xp1 * xx  * xm2 * 0.5f;
                    float w3 =  xp1 * xx  * xm1 * (1.f / 6.f);
                    float a0 = w0 * P.x, a1 = w1 * P.y, a2 = w2 * P.z, a3 = w3 * P.w;
                    f = (a0 + a1) + (a2 + a3);
                    o[t0 + i] = f;
                }
            }
        }
    }
}

extern "C" void kernel_launch(void* const* d_in, const int* in_sizes, int n_in,
                              void* d_out, int out_size) {
    const float* x     = (const float*)d_in[0];
    // d_in[1] timestamp: unused
    const float* gamma = (const float*)d_in[2];
    const float* beta  = (const float*)d_in[3];
    const float* Wih0  = (const float*)d_in[4];
    const float* bih0  = (const float*)d_in[5];
    // d_in[6] W_hh0 unused (h_prev = 0)
    const float* bhh0  = (const float*)d_in[7];
    const float* Wih1  = (const float*)d_in[8];
    const float* bih1  = (const float*)d_in[9];
    // d_in[10] W_hh1 unused
    const float* bhh1  = (const float*)d_in[11];
    const float* Wp    = (const float*)d_in[12];
    const float* bp    = (const float*)d_in[13];
    float* out = (float*)d_out;

    k_stats<<<dim3(4, 64), 256>>>(x);
    k_finalize<<<1, 1024>>>(gamma, beta, Wp, bp);
    k_px<<<BT / 8, 256>>>(x);
    k_tabscan<<<GRID, NTHR>>>(Wih0, bih0, bhh0, Wih1, bih1, bhh1, Wp, bp, out);
}

// round 11
// speedup vs baseline: 1.7660x; 1.0431x over previous
#include <cuda_runtime.h>
#include <cuda_fp16.h>
#include <mma.h>
#include <math.h>
#include <cstdint>

using namespace nvcuda;

#define BB 64
#define TT 512
#define HH 1024
#define BT (BB*TT)
#define NF 128
#define N3H (3*HH)
#define NCHUNK 64
#define ROWS_PER_CHUNK (BT/NCHUNK)  // 512
#define GRID 148
#define NTHR 512

// ---------------- device scratch (no allocations allowed) ----------------
__device__ float g_part_sum[NCHUNK][HH];
__device__ float g_part_sq[NCHUNK][HH];
__device__ float g_a[HH];
__device__ float g_C;
__device__ float g_WpL1;            // sum|Wp| + |bp|
__device__ unsigned g_pxmax_u;
__device__ float g_pxT[TT][BB];     // px transposed [t][b]
__device__ float g_phi[NF][HH];
__device__ float g_gip[2][NF][N3H]; // 2-way K-split GEMM partials
__device__ float g_Ftab[NF];

// ---------------- grid-wide barrier (148 CTAs, 1/SM) ----------------
__device__ unsigned g_bar_count = 0;
__device__ volatile unsigned g_bar_gen = 0;

__device__ __forceinline__ void grid_sync() {
    __syncthreads();
    if (threadIdx.x == 0) {
        __threadfence();
        unsigned gen = g_bar_gen;
        if (atomicAdd(&g_bar_count, 1u) == GRID - 1) {
            g_bar_count = 0;
            __threadfence();
            g_bar_gen = gen + 1;
        } else {
            while (g_bar_gen == gen) { }
        }
        __threadfence();
    }
    __syncthreads();
}

__device__ __forceinline__ void half_bar(int id) {
    asm volatile("bar.sync %0, 256;" :: "r"(id) : "memory");
}

__device__ __forceinline__ float load_R() {
    float wl = __ldcg(&g_WpL1);
    float pxmax = __uint_as_float(__ldcg((const unsigned*)&g_pxmax_u));
    return 0.5f * (pxmax + wl) * 1.02f + 0.25f;
}

__device__ __forceinline__ uint32_t smem_u32(const void* p) {
    uint32_t a;
    asm("{ .reg .u64 t; cvta.to.shared.u64 t, %1; cvt.u32.u64 %0, t; }" : "=r"(a) : "l"(p));
    return a;
}

// ================= pass 1: BN partial sums =================
__global__ void k_stats(const float* __restrict__ x) {
    int ch = blockIdx.x * 256 + threadIdx.x;
    int r0 = blockIdx.y * ROWS_PER_CHUNK;
    const float* p = x + (size_t)r0 * HH + ch;
    float s = 0.f, q = 0.f;
#pragma unroll 16
    for (int r = 0; r < ROWS_PER_CHUNK; r++) {
        float v = p[(size_t)r * HH];
        s += v; q += v * v;
    }
    g_part_sum[blockIdx.y][ch] = s;
    g_part_sq[blockIdx.y][ch]  = q;
}

// ================= finalize -> a[], C, WpL1; reset pxmax =================
__global__ void k_finalize(const float* __restrict__ gamma, const float* __restrict__ beta,
                           const float* __restrict__ Wp, const float* __restrict__ bp) {
    int j = threadIdx.x;  // 1024
    float s = 0.f, q = 0.f;
#pragma unroll 8
    for (int c = 0; c < NCHUNK; c++) { s += g_part_sum[c][j]; q += g_part_sq[c][j]; }
    float mean = s * (1.0f / BT);
    float var  = q * (1.0f / BT) - mean * mean;
    float rstd = rsqrtf(var + 1e-5f);
    float gj = gamma[j], wj = Wp[j];
    g_a[j] = gj * rstd * wj;
    float cj = (beta[j] - mean * rstd * gj) * wj;
    float aw = fabsf(wj);
    __shared__ float sc[1024], sa[1024];
    sc[j] = cj; sa[j] = aw;
    __syncthreads();
    for (int st = 512; st > 0; st >>= 1) {
        if (j < st) { sc[j] += sc[j + st]; sa[j] += sa[j + st]; }
        __syncthreads();
    }
    if (j == 0) {
        g_C = sc[0] + bp[0];
        g_WpL1 = sa[0] + fabsf(bp[0]);
        g_pxmax_u = 0u;
    }
}

// ================= pass 2: px -> transposed store + global max =================
__global__ void k_px(const float* __restrict__ x) {
    int w = threadIdx.x >> 5, lane = threadIdx.x & 31;
    int r = blockIdx.x * 8 + w;
    const float4* xr = (const float4*)(x + (size_t)r * HH);
    const float4* a4 = (const float4*)g_a;
    float acc = 0.f;
#pragma unroll
    for (int i = 0; i < 8; i++) {
        float4 xv = xr[lane + i * 32];
        float4 av = __ldg(&a4[lane + i * 32]);
        acc += xv.x * av.x + xv.y * av.y + xv.z * av.z + xv.w * av.w;
    }
#pragma unroll
    for (int off = 16; off; off >>= 1) acc += __shfl_down_sync(0xFFFFFFFFu, acc, off);
    __shared__ float wm[8];
    if (lane == 0) {
        float v = acc + g_C;
        g_pxT[r & (TT - 1)][r >> 9] = v;
        wm[w] = fabsf(v);
    }
    __syncthreads();
    if (threadIdx.x == 0) {
        float m = wm[0];
#pragma unroll
        for (int i = 1; i < 8; i++) m = fmaxf(m, wm[i]);
        atomicMax(&g_pxmax_u, __float_as_uint(m));
    }
}

// ================= fused table build: phi -> fp16 WMMA GEMM -> tail =================
#define LDMH 72

__global__ void __launch_bounds__(NTHR, 1) k_table(
    const float* __restrict__ W0, const float* __restrict__ bih0,
    const float* __restrict__ bhh0,
    const float* __restrict__ W1, const float* __restrict__ bih1,
    const float* __restrict__ bhh1,
    const float* __restrict__ Wp, const float* __restrict__ bp)
{
    __shared__ __align__(16) char s_mem[36992];
    float* s_buf = (float*)s_mem;
    int b = blockIdx.x, tid = threadIdx.x;

    // ---- phase A: phi table (layer-0 GRU cell, h=0) ----
    {
        float R = load_R();
        float s0v = -R, delta = 2.f * R / (float)(NF - 1);
        for (int idx = b * NTHR + tid; idx < NF * HH; idx += GRID * NTHR) {
            int i = idx >> 10, j = idx & (HH - 1);
            float s = s0v + (float)i * delta;
            float ar = fmaf(s, W0[j],          bih0[j]        + bhh0[j]);
            float az = fmaf(s, W0[HH + j],     bih0[HH + j]   + bhh0[HH + j]);
            float r = 1.f / (1.f + expf(-ar));
            float z = 1.f / (1.f + expf(-az));
            float an = fmaf(s, W0[2*HH + j], fmaf(r, bhh0[2*HH + j], bih0[2*HH + j]));
            g_phi[i][j] = (1.f - z) * tanhf(an);
        }
    }
    grid_sync();

    // ---- phase B: fp16 WMMA GEMM, 192 jobs 64x64xK512, register double-buffer ----
    {
        int half = tid >> 8;
        int ltid = tid & 255;
        int job = b + half * GRID;
        if (job < 192) {
            __half (*As)[LDMH] = (__half(*)[LDMH])(s_mem + half * 18496);
            __half (*Bs)[LDMH] = (__half(*)[LDMH])(s_mem + half * 18496 + 9248);
            int kseg = job / 96, rem = job % 96;
            int m0 = (rem & 1) * 64, n0 = (rem >> 1) * 64;
            int w = ltid >> 5;
            int wm = w >> 1, wn = w & 1;    // 4 x 2 warp grid, warp tile 16x32
            int sr = ltid >> 2;
            int sc = (ltid & 3) * 16;

            wmma::fragment<wmma::accumulator, 16, 16, 16, float> acc[2];
            wmma::fill_fragment(acc[0], 0.0f);
            wmma::fill_fragment(acc[1], 0.0f);

            float4 ra[4], rb[4];
            {   // prefetch chunk 0
                int k0 = kseg * 512;
                const float4* pa = (const float4*)&g_phi[m0 + sr][k0] + (sc >> 2);
                const float4* pb = (const float4*)&W1[(size_t)(n0 + sr) * HH + k0] + (sc >> 2);
#pragma unroll
                for (int j = 0; j < 4; j++) { ra[j] = pa[j]; rb[j] = pb[j]; }
            }
            for (int kc = 0; kc < 8; kc++) {
                half_bar(half + 1);          // previous chunk's readers done
#pragma unroll
                for (int j = 0; j < 4; j++) {
                    union { __half2 h[2]; uint2 u; } t;
                    t.h[0] = __floats2half2_rn(ra[j].x, ra[j].y);
                    t.h[1] = __floats2half2_rn(ra[j].z, ra[j].w);
                    *(uint2*)&As[sr][sc + j * 4] = t.u;
                    t.h[0] = __floats2half2_rn(rb[j].x, rb[j].y);
                    t.h[1] = __floats2half2_rn(rb[j].z, rb[j].w);
                    *(uint2*)&Bs[sr][sc + j * 4] = t.u;
                }
                half_bar(half + 1);          // tiles staged
                if (kc < 7) {                // prefetch next chunk; latency overlaps MMAs
                    int k0 = kseg * 512 + (kc + 1) * 64;
                    const float4* pa = (const float4*)&g_phi[m0 + sr][k0] + (sc >> 2);
                    const float4* pb = (const float4*)&W1[(size_t)(n0 + sr) * HH + k0] + (sc >> 2);
#pragma unroll
                    for (int j = 0; j < 4; j++) { ra[j] = pa[j]; rb[j] = pb[j]; }
                }
#pragma unroll
                for (int ks = 0; ks < 4; ks++) {
                    int kk = ks * 16;
                    wmma::fragment<wmma::matrix_a, 16, 16, 16, __half, wmma::row_major> fa;
                    wmma::fragment<wmma::matrix_b, 16, 16, 16, __half, wmma::col_major> fb0, fb1;
                    wmma::load_matrix_sync(fa,  &As[wm * 16][kk], LDMH);
                    wmma::load_matrix_sync(fb0, &Bs[wn * 32][kk], LDMH);
                    wmma::load_matrix_sync(fb1, &Bs[wn * 32 + 16][kk], LDMH);
                    wmma::mma_sync(acc[0], fa, fb0, acc[0]);
                    wmma::mma_sync(acc[1], fa, fb1, acc[1]);
                }
            }
            wmma::store_matrix_sync(&g_gip[kseg][m0 + wm * 16][n0 + wn * 32],
                                    acc[0], N3H, wmma::mem_row_major);
            wmma::store_matrix_sync(&g_gip[kseg][m0 + wm * 16][n0 + wn * 32 + 16],
                                    acc[1], N3H, wmma::mem_row_major);
        }
    }
    grid_sync();

    // ---- phase C: sum K-partials + layer-1 nonlin + projection (blocks 0..127) ----
    if (b < NF) {
        float acc = 0.f;
        for (int ch = tid; ch < HH; ch += NTHR) {
            float gr = (__ldcg(&g_gip[0][b][ch])        + __ldcg(&g_gip[1][b][ch]))        + bih1[ch];
            float gz = (__ldcg(&g_gip[0][b][HH + ch])   + __ldcg(&g_gip[1][b][HH + ch]))   + bih1[HH + ch];
            float gn = (__ldcg(&g_gip[0][b][2*HH + ch]) + __ldcg(&g_gip[1][b][2*HH + ch])) + bih1[2*HH + ch];
            float r = 1.f / (1.f + expf(-(gr + bhh1[ch])));
            float z = 1.f / (1.f + expf(-(gz + bhh1[HH + ch])));
            float n = tanhf(gn + r * bhh1[2*HH + ch]);
            acc += Wp[ch] * (1.f - z) * n;
        }
        s_buf[tid] = acc;
        __syncthreads();
        for (int st = 256; st > 0; st >>= 1) {
            if (tid < st) s_buf[tid] += s_buf[tid + st];
            __syncthreads();
        }
        if (tid == 0) g_Ftab[b] = s_buf[0] + bp[0];
    }
}

// ================= sequential scan: 64 scalar recurrences =================
__global__ void __launch_bounds__(64) k_scan(const float* __restrict__ bp,
                                             float* __restrict__ out) {
    __shared__ __align__(16) float4 tab[NF];   // per-cell monomial coeffs {c0,c1,c2,c3}
    int tid = threadIdx.x;  // 64
    // stage: convert F values -> cubic coefficients in y (nodes -1.5,-0.5,0.5,1.5)
    for (int i = tid; i < NF; i += 64) {
        float a = __ldcg(&g_Ftab[i > 0 ? i - 1 : 0]);
        float bb = __ldcg(&g_Ftab[i]);
        float c = __ldcg(&g_Ftab[i < NF - 1 ? i + 1 : NF - 1]);
        float d = __ldcg(&g_Ftab[i < NF - 2 ? i + 2 : NF - 1]);
        float c0 = (-a + 9.f*bb + 9.f*c - d) * (1.f/16.f);
        float c1 = (a - d) * (1.f/24.f) + (c - bb) * (9.f/8.f);
        float c2 = (a - bb - c + d) * 0.25f;
        float c3 = (-a + 3.f*bb - 3.f*c + d) * (1.f/6.f);
        tab[i] = make_float4(c0, c1, c2, c3);
    }
    float R = load_R();
    float invd = (float)(NF - 1) / (2.f * R);
    float k1 = 0.5f * invd;
    float base = R * invd - 0.5f;          // -0.5: round(u) == floor(true_u)
    __syncthreads();
    const float MAGIC = 12582912.0f;       // 2^23 + 2^22, bits 0x4B400000
    // addr = float_bits(u + MAGIC)*16 + adj  (u32 wrap folds away the constant high bits)
    uint32_t adj = smem_u32(tab) - (0x4B400000u << 4);
    float* o = out + tid * TT;
    float f = 0.f;
    float buf[8];
#pragma unroll
    for (int i = 0; i < 8; i++) buf[i] = __ldcg(&g_pxT[i][tid]);
    for (int t0 = 0; t0 < TT; t0 += 8) {
#pragma unroll
        for (int i = 0; i < 8; i++) {
            float pxv = buf[i];
            int tn = t0 + 8 + i;
            if (tn < TT) buf[i] = __ldcg(&g_pxT[tn][tid]);   // off the f-chain
            float pb = fmaf(pxv, k1, base);                  // independent of f
            float u = fmaf(f, k1, pb);                       // chain: FFMA
            float fm = u + MAGIC;                            // chain: FADD
            uint32_t addr = __float_as_uint(fm) * 16u + adj; // chain: IMAD
            float4 P;
            asm volatile("ld.shared.v4.f32 {%0,%1,%2,%3}, [%4];"
                         : "=f"(P.x), "=f"(P.y), "=f"(P.z), "=f"(P.w) : "r"(addr));
            float y = u - (fm - MAGIC);                      // parallel, ready @12
            float q = y * y;                                 // ready @16 << LDS @41
            float A  = fmaf(P.y, y, P.x);                    // Estrin
            float Bv = fmaf(P.w, y, P.z);
            f = fmaf(q, Bv, A);                              // chain: 8 cyc post-LDS
            o[t0 + i] = f;
        }
    }
}

extern "C" void kernel_launch(void* const* d_in, const int* in_sizes, int n_in,
                              void* d_out, int out_size) {
    const float* x     = (const float*)d_in[0];
    // d_in[1] timestamp: unused
    const float* gamma = (const float*)d_in[2];
    const float* beta  = (const float*)d_in[3];
    const float* Wih0  = (const float*)d_in[4];
    const float* bih0  = (const float*)d_in[5];
    // d_in[6] W_hh0 unused (h_prev = 0)
    const float* bhh0  = (const float*)d_in[7];
    const float* Wih1  = (const float*)d_in[8];
    const float* bih1  = (const float*)d_in[9];
    // d_in[10] W_hh1 unused
    const float* bhh1  = (const float*)d_in[11];
    const float* Wp    = (const float*)d_in[12];
    const float* bp    = (const float*)d_in[13];
    float* out = (float*)d_out;

    k_stats<<<dim3(4, 64), 256>>>(x);
    k_finalize<<<1, 1024>>>(gamma, beta, Wp, bp);
    k_px<<<BT / 8, 256>>>(x);
    k_table<<<GRID, NTHR>>>(Wih0, bih0, bhh0, Wih1, bih1, bhh1, Wp, bp);
    k_scan<<<1, 64>>>(bp, out);
}